// round 11
// baseline (speedup 1.0000x reference)
#include <cuda_runtime.h>
#include <cuda_bf16.h>
#include <cuda_fp16.h>
#include <math.h>
#include <float.h>

// Problem constants
#define Bq   4
#define Tq   16
#define Sq   4096
#define Hq   32
#define KVq  8
#define Dq   128
#define DIMq 4096
#define HD   (Hq*Dq)          // 4096
#define KVD  (KVq*Dq)         // 1024
#define NTOT (HD + 2*KVD)     // 6144
#define M64  (Bq*Tq)          // 64
#define GQ   (Hq/KVq)         // 4
#define AROWS 64
#define NSPLIT 8
#define SCALE_F 0.08838834764831843f
#define SPLITK  8             // qkv
#define SPLITKO 16            // out proj

// ---------------- scratch ----------------------------------------------------
__device__ float g_qkvp[SPLITK][M64 * NTOT];
__device__ float g_outp[SPLITKO][M64 * DIMq];
__device__ float g_qatt[Bq*KVq*AROWS*Dq];
__device__ unsigned g_khw[(size_t)Bq*KVq*Sq*64];    // packed fp16 K (fragment order)
__device__ unsigned g_vhw[(size_t)Bq*KVq*(Sq/2)*128]; // packed fp16 V (key pairs)
__device__ float g_pacc[(size_t)NSPLIT*Bq*KVq*AROWS*Dq];
__device__ float g_pm  [NSPLIT*Bq*KVq*AROWS];
__device__ float g_pl  [NSPLIT*Bq*KVq*AROWS];
__device__ float g_y   [M64 * HD];

// ================= shared helpers ===========================================
__device__ __forceinline__ unsigned smem_u32(const void* p) {
    unsigned a;
    asm("{ .reg .u64 t; cvta.to.shared.u64 t, %1; cvt.u32.u64 %0, t; }"
        : "=r"(a) : "l"(p));
    return a;
}
__device__ __forceinline__ unsigned f2tf32(float x) {
    unsigned u; asm("cvt.rna.tf32.f32 %0, %1;" : "=r"(u) : "f"(x)); return u;
}
__device__ __forceinline__ unsigned h2pack(float lo, float hi) {
    unsigned r; asm("cvt.rn.f16x2.f32 %0, %1, %2;" : "=r"(r) : "f"(hi), "f"(lo));
    return r;
}
__device__ __forceinline__ void mma_tf32(float c[4], const unsigned a[4], const unsigned b[2]) {
    asm volatile(
        "mma.sync.aligned.m16n8k8.row.col.f32.tf32.tf32.f32 "
        "{%0,%1,%2,%3}, {%4,%5,%6,%7}, {%8,%9}, {%0,%1,%2,%3};\n"
        : "+f"(c[0]), "+f"(c[1]), "+f"(c[2]), "+f"(c[3])
        : "r"(a[0]), "r"(a[1]), "r"(a[2]), "r"(a[3]), "r"(b[0]), "r"(b[1]));
}
__device__ __forceinline__ void mma_f16(float c[4], const unsigned a[4], const unsigned b[2]) {
    asm volatile(
        "mma.sync.aligned.m16n8k16.row.col.f32.f16.f16.f32 "
        "{%0,%1,%2,%3}, {%4,%5,%6,%7}, {%8,%9}, {%0,%1,%2,%3};\n"
        : "+f"(c[0]), "+f"(c[1]), "+f"(c[2]), "+f"(c[3])
        : "r"(a[0]), "r"(a[1]), "r"(a[2]), "r"(a[3]), "r"(b[0]), "r"(b[1]));
}
__device__ __forceinline__ void cpasync16(unsigned saddr, const void* g) {
    asm volatile("cp.async.ca.shared.global [%0], [%1], 16;" :: "r"(saddr), "l"(g));
}
__device__ __forceinline__ unsigned lds32(unsigned baddr) {
    unsigned x; asm volatile("ld.shared.u32 %0, [%1];" : "=r"(x) : "r"(baddr));
    return x;
}
__device__ __forceinline__ void lds64(unsigned &x, unsigned &y, unsigned baddr) {
    asm volatile("ld.shared.v2.u32 {%0, %1}, [%2];" : "=r"(x), "=r"(y) : "r"(baddr));
}

// ================= tf32 split-K GEMM, 64x128 block tile, 3-stage ============
#define BKg      32
#define GSTAGES  3
#define GSTRIDE  36
#define GSTG_FLT (192 * GSTRIDE)
#define GEMM_SMEM_BYTES (GSTAGES * GSTG_FLT * 4)   // 82944
#define GK       4096

__device__ __forceinline__ void gemm_tile_mma(const float* __restrict__ A,
                                              const float* __restrict__ W,
                                              float* __restrict__ Cbase,
                                              int ldc, int kbeg, int nks) {
    extern __shared__ float smf[];
    const int tid  = threadIdx.x;
    const int lane = tid & 31;
    const int wid  = tid >> 5;
    const int gid  = lane >> 2;
    const int ctg  = lane & 3;
    const int wm   = wid & 1;
    const int wn   = wid >> 1;
    const int frA  = tid >> 2;
    const int fkA  = (tid & 3) * 8;
    const int frW  = tid >> 1;
    const int fkW  = (tid & 1) * 16;
    const unsigned sbase = smem_u32(smf);

    float acc[2][4][4];
#pragma unroll
    for (int mi = 0; mi < 2; mi++)
#pragma unroll
        for (int ni = 0; ni < 4; ni++)
#pragma unroll
            for (int j = 0; j < 4; j++) acc[mi][ni][j] = 0.f;

#pragma unroll
    for (int s = 0; s < GSTAGES - 1; s++) {
        unsigned sa = sbase + (unsigned)(s * GSTG_FLT + frA * GSTRIDE + fkA) * 4u;
        unsigned sw = sbase + (unsigned)(s * GSTG_FLT + (64 + frW) * GSTRIDE + fkW) * 4u;
        const float* ga = A + (size_t)frA * GK + kbeg + s * BKg + fkA;
        const float* gw = W + (size_t)frW * GK + kbeg + s * BKg + fkW;
        cpasync16(sa, ga);       cpasync16(sa + 16, ga + 4);
        cpasync16(sw, gw);       cpasync16(sw + 16, gw + 4);
        cpasync16(sw + 32, gw + 8); cpasync16(sw + 48, gw + 12);
        asm volatile("cp.async.commit_group;");
    }

    for (int i = 0; i < nks; i++) {
        asm volatile("cp.async.wait_group 1;");
        __syncthreads();
        int bufi = i % 3;
        const float* As = smf + bufi * GSTG_FLT;
        const float* Ws = As + 64 * GSTRIDE;

#pragma unroll
        for (int ks = 0; ks < 4; ks++) {
            const int k = ks * 8;
            unsigned af[2][4], bf[4][2];
#pragma unroll
            for (int mi = 0; mi < 2; mi++) {
                int r = wm * 32 + mi * 16 + gid;
                af[mi][0] = f2tf32(As[r * GSTRIDE + k + ctg]);
                af[mi][1] = f2tf32(As[(r + 8) * GSTRIDE + k + ctg]);
                af[mi][2] = f2tf32(As[r * GSTRIDE + k + ctg + 4]);
                af[mi][3] = f2tf32(As[(r + 8) * GSTRIDE + k + ctg + 4]);
            }
#pragma unroll
            for (int ni = 0; ni < 4; ni++) {
                int n = wn * 32 + ni * 8 + gid;
                bf[ni][0] = f2tf32(Ws[n * GSTRIDE + k + ctg]);
                bf[ni][1] = f2tf32(Ws[n * GSTRIDE + k + ctg + 4]);
            }
#pragma unroll
            for (int mi = 0; mi < 2; mi++)
#pragma unroll
                for (int ni = 0; ni < 4; ni++)
                    mma_tf32(acc[mi][ni], af[mi], bf[ni]);
        }

        if (i + GSTAGES - 1 < nks) {
            int s = (i + 2) % 3;
            int k0 = kbeg + (i + 2) * BKg;
            unsigned sa = sbase + (unsigned)(s * GSTG_FLT + frA * GSTRIDE + fkA) * 4u;
            unsigned sw = sbase + (unsigned)(s * GSTG_FLT + (64 + frW) * GSTRIDE + fkW) * 4u;
            const float* ga = A + (size_t)frA * GK + k0 + fkA;
            const float* gw = W + (size_t)frW * GK + k0 + fkW;
            cpasync16(sa, ga);       cpasync16(sa + 16, ga + 4);
            cpasync16(sw, gw);       cpasync16(sw + 16, gw + 4);
            cpasync16(sw + 32, gw + 8); cpasync16(sw + 48, gw + 12);
            asm volatile("cp.async.commit_group;");
        } else {
            asm volatile("cp.async.commit_group;");
        }
    }

#pragma unroll
    for (int mi = 0; mi < 2; mi++)
#pragma unroll
        for (int ni = 0; ni < 4; ni++) {
            int r0 = wm * 32 + mi * 16 + gid;
            int c0 = wn * 32 + ni * 8 + 2 * ctg;
            *reinterpret_cast<float2*>(&Cbase[(size_t)r0 * ldc + c0]) =
                make_float2(acc[mi][ni][0], acc[mi][ni][1]);
            *reinterpret_cast<float2*>(&Cbase[(size_t)(r0 + 8) * ldc + c0]) =
                make_float2(acc[mi][ni][2], acc[mi][ni][3]);
        }
}

__global__ void qkv_kernel(const float* __restrict__ x,
                           const float* __restrict__ wq,
                           const float* __restrict__ wk,
                           const float* __restrict__ wv) {
    int n0 = blockIdx.x * 128;
    int sp = blockIdx.y;
    const float* W;
    if (n0 < HD)            W = wq + (size_t)n0 * DIMq;
    else if (n0 < HD + KVD) W = wk + (size_t)(n0 - HD) * DIMq;
    else                    W = wv + (size_t)(n0 - HD - KVD) * DIMq;
    gemm_tile_mma(x, W, g_qkvp[sp] + n0, NTOT, sp * (GK / SPLITK), GK / BKg / SPLITK);
}

__global__ void out_kernel(const float* __restrict__ wo) {
    int n0 = blockIdx.x * 128;
    int sp = blockIdx.y;
    gemm_tile_mma(g_y, wo + (size_t)n0 * DIMq, g_outp[sp] + n0, DIMq,
                  sp * (GK / SPLITKO), GK / BKg / SPLITKO);
}

__global__ void reduce_out_kernel(float* __restrict__ out) {
    int i = blockIdx.x * 256 + threadIdx.x;
    if (i >= M64 * DIMq / 4) return;
    float4 r = reinterpret_cast<const float4*>(g_outp[0])[i];
#pragma unroll
    for (int sp = 1; sp < SPLITKO; sp++) {
        float4 v = reinterpret_cast<const float4*>(g_outp[sp])[i];
        r.x += v.x; r.y += v.y; r.z += v.z; r.w += v.w;
    }
    reinterpret_cast<float4*>(out)[i] = r;
}

// ---------------- rope Q (split-K reduce fused) ------------------------------
#define QPAIRS (M64*Hq*(Dq/2))   // 131072
__global__ void rope_q_kernel(const float* __restrict__ fc,
                              const float* __restrict__ fs) {
    int idx = blockIdx.x * blockDim.x + threadIdx.x;
    if (idx >= QPAIRS) return;
    int i = idx & 63;
    int h = (idx >> 6) & (Hq - 1);
    int m = idx >> 11;
    int t = m & (Tq - 1), b = m >> 4;
    size_t off = (size_t)m * NTOT + h * Dq + 2 * i;
    float x0 = 0.f, x1 = 0.f;
#pragma unroll
    for (int sp = 0; sp < SPLITK; sp++) {
        float2 p = *reinterpret_cast<const float2*>(&g_qkvp[sp][off]);
        x0 += p.x; x1 += p.y;
    }
    float c = fc[t * 64 + i], s = fs[t * 64 + i];
    int kv = h >> 2, hl = h & 3;
    float* q = g_qatt + ((((size_t)b * KVq + kv) * AROWS) + hl * Tq + t) * Dq + 2 * i;
    q[0] = (x0 * c - x1 * s) * SCALE_F;
    q[1] = (x0 * s + x1 * c) * SCALE_F;
}

// ---------------- cvt_kv: cache + new tokens -> packed fp16 -----------------
// z=0: K rows (permuted fragment word order), z=1: V pair-rows.
// New-token K rows get RoPE applied from split-K partials (replaces rope_kv).
__global__ void cvt_kv_kernel(const float* __restrict__ k_cache,
                              const float* __restrict__ v_cache,
                              const float* __restrict__ fc,
                              const float* __restrict__ fs,
                              const int* __restrict__ input_pos) {
    const int y = blockIdx.y;
    const int b = y >> 3, kv = y & 7;
    const int start = __ldg(&input_pos[0]);
    const int limit = __ldg(&input_pos[Tq - 1]) + 1;
    const int wi = blockIdx.x * 256 + threadIdx.x;

    if (blockIdx.z == 0) {
        int s = wi >> 6;
        if (s >= limit) return;
        int w6 = wi & 63;
        int c = w6 >> 3, w = w6 & 7;
        int d0 = c * 16 + (w >> 1) * 2 + (w & 1) * 8;
        float k0, k1;
        if (s < start) {
            size_t base = (((size_t)b * Sq + s) * KVq + kv) * Dq + d0;
            k0 = k_cache[base]; k1 = k_cache[base + 1];
        } else {
            int t = s - start;
            size_t off = (size_t)(b * Tq + t) * NTOT + HD + kv * Dq + d0;
            float x0 = 0.f, x1 = 0.f;
#pragma unroll
            for (int sp = 0; sp < SPLITK; sp++) {
                float2 p = *reinterpret_cast<const float2*>(&g_qkvp[sp][off]);
                x0 += p.x; x1 += p.y;
            }
            int i = d0 >> 1;
            float cc = fc[t * 64 + i], ss = fs[t * 64 + i];
            k0 = x0 * cc - x1 * ss;
            k1 = x0 * ss + x1 * cc;
        }
        g_khw[((size_t)(b * KVq + kv) * Sq + s) * 64 + w6] = h2pack(k0, k1);
    } else {
        int sp_ = wi >> 7;
        int d = wi & 127;
        int s0 = 2 * sp_;
        if (s0 >= limit) return;
        int s1 = s0 + 1;
        float v0, v1 = 0.f;
        if (s0 < start) {
            v0 = v_cache[(((size_t)b * Sq + s0) * KVq + kv) * Dq + d];
        } else {
            size_t off = (size_t)(b * Tq + (s0 - start)) * NTOT + HD + KVD + kv * Dq + d;
            v0 = 0.f;
#pragma unroll
            for (int sp = 0; sp < SPLITK; sp++) v0 += g_qkvp[sp][off];
        }
        if (s1 < limit) {
            if (s1 < start) {
                v1 = v_cache[(((size_t)b * Sq + s1) * KVq + kv) * Dq + d];
            } else {
                size_t off = (size_t)(b * Tq + (s1 - start)) * NTOT + HD + KVD + kv * Dq + d;
                v1 = 0.f;
#pragma unroll
                for (int sp = 0; sp < SPLITK; sp++) v1 += g_qkvp[sp][off];
            }
        }
        g_vhw[((size_t)(b * KVq + kv) * (Sq / 2) + sp_) * 128 + d] = h2pack(v0, v1);
    }
}

// ================= tensor-core flash attention v6 ===========================
// 128 threads / 4 warps, warp owns 16 q-rows x all 64 keys of a tile.
// K/V arrive pre-packed fp16 via cp.async double buffer (no prefetch regs,
// no cvt). K fragment = LDS.64, V fragment = 2x LDS.32 (conflict-light).
#define KV_TILE 64
#define KROWW 72                           // K row stride (words)
#define VROWW 136                          // V pair-row stride (words)
#define BUFW  (64*KROWW + 32*VROWW)        // 8960 words per buffer
#define VOFFW (64*KROWW)                   // 4608
#define ATTN_SMEM_BYTES (2 * BUFW * 4)     // 71680

__global__ void __launch_bounds__(128, 3)
attn_kernel(const int* __restrict__ input_pos) {
    extern __shared__ unsigned smemU[];
    __shared__ int pos_s[Tq];

    const int tid  = threadIdx.x;
    const int lane = tid & 31;
    const int gid  = lane >> 2;
    const int ctg  = lane & 3;
    const int wid  = tid >> 5;
    const int r0   = wid * 16 + gid;

    const int bk = blockIdx.x & 31;
    const int split = blockIdx.x >> 5;
    const int b = bk >> 3, kv = bk & 7;

    if (tid < Tq) pos_s[tid] = input_pos[tid];

    const int limit = __ldg(&input_pos[Tq - 1]) + 1;
    const int totalTiles = (limit + KV_TILE - 1) / KV_TILE;
    const int tbase = totalTiles / NSPLIT, trem = totalTiles % NSPLIT;
    const int t0 = split * tbase + min(split, trem);
    const int tcount = tbase + (split < trem);
    const int sbeg = t0 * KV_TILE;
    const int send = min((t0 + tcount) * KV_TILE, limit);

    // ---- Q into fp16 registers: 8 k16-chunks x 4 regs ----
    unsigned qreg[8][4];
    {
        const float* qa = g_qatt + (((size_t)b * KVq + kv) * AROWS + r0) * Dq;
        const float* qb = qa + 8 * Dq;
#pragma unroll
        for (int ks = 0; ks < 8; ks++) {
            int c0 = ks * 16 + 2 * ctg;
            qreg[ks][0] = h2pack(qa[c0],     qa[c0 + 1]);
            qreg[ks][1] = h2pack(qb[c0],     qb[c0 + 1]);
            qreg[ks][2] = h2pack(qa[c0 + 8], qa[c0 + 9]);
            qreg[ks][3] = h2pack(qb[c0 + 8], qb[c0 + 9]);
        }
    }

    const unsigned sb = smem_u32(smemU);
    const unsigned* khbase = g_khw + (size_t)(b * KVq + kv) * Sq * 64;
    const unsigned* vhbase = g_vhw + (size_t)(b * KVq + kv) * (Sq / 2) * 128;

    // cp.async fill mapping: K thread t -> row t>>1, half t&1 (8 chunks);
    // V thread t -> pair-row t>>2, quarter t&3 (8 chunks).
    const int krr = tid >> 1, krh = tid & 1;
    const int vrr = tid >> 2, vrq = tid & 3;

    auto issue_tile = [&](int tile, int buf) {
        int s0t = sbeg + tile * KV_TILE;
        unsigned kdst = sb + (unsigned)(buf * BUFW + krr * KROWW + krh * 32) * 4u;
        const unsigned* ksrc = khbase + (size_t)(s0t + krr) * 64 + krh * 32;
#pragma unroll
        for (int j = 0; j < 8; j++)
            cpasync16(kdst + j * 16u, ksrc + j * 4);
        unsigned vdst = sb + (unsigned)(buf * BUFW + VOFFW + vrr * VROWW + vrq * 32) * 4u;
        const unsigned* vsrc = vhbase + (size_t)(s0t / 2 + vrr) * 128 + vrq * 32;
#pragma unroll
        for (int j = 0; j < 8; j++)
            cpasync16(vdst + j * 16u, vsrc + j * 4);
    };

    if (tcount > 0) issue_tile(0, 0);
    asm volatile("cp.async.commit_group;");
    if (tcount > 1) issue_tile(1, 1);
    asm volatile("cp.async.commit_group;");

    float acc[16][4];
#pragma unroll
    for (int nt = 0; nt < 16; nt++)
#pragma unroll
        for (int j = 0; j < 4; j++) acc[nt][j] = 0.f;
    float m0 = -FLT_MAX, m1 = -FLT_MAX, l0 = 0.f, l1 = 0.f;

    for (int t = 0; t < tcount; t++) {
        const int s0 = sbeg + t * KV_TILE;
        const int buf = t & 1;
        asm volatile("cp.async.wait_group 1;");
        __syncthreads();                        // tile t visible to all warps

        const unsigned kbB = sb + (unsigned)(buf * BUFW) * 4u;
        const unsigned vbB = sb + (unsigned)(buf * BUFW + VOFFW) * 4u;

        // ---- QK^T: 16 rows x 64 keys ----
        float sc[8][4];
#pragma unroll
        for (int nt = 0; nt < 8; nt++)
#pragma unroll
            for (int j = 0; j < 4; j++) sc[nt][j] = 0.f;
#pragma unroll
        for (int ks = 0; ks < 8; ks++) {
#pragma unroll
            for (int nt = 0; nt < 8; nt++) {
                int key = nt * 8 + gid;
                unsigned bfr[2];
                lds64(bfr[0], bfr[1],
                      kbB + (unsigned)(key * KROWW + ks * 8 + ctg * 2) * 4u);
                mma_f16(sc[nt], qreg[ks], bfr);
            }
        }

        // ---- mask + warp-local online softmax (registers + quad shfl) ----
        const int p0 = pos_s[gid];
        const int p1 = pos_s[gid + 8];
        float tm0 = -FLT_MAX, tm1 = -FLT_MAX;
#pragma unroll
        for (int nt = 0; nt < 8; nt++) {
            int cb = nt * 8 + 2 * ctg;
            int sA = s0 + cb, sB = sA + 1;
            sc[nt][0] = (sA < send && sA <= p0) ? sc[nt][0] : -FLT_MAX;
            sc[nt][1] = (sB < send && sB <= p0) ? sc[nt][1] : -FLT_MAX;
            sc[nt][2] = (sA < send && sA <= p1) ? sc[nt][2] : -FLT_MAX;
            sc[nt][3] = (sB < send && sB <= p1) ? sc[nt][3] : -FLT_MAX;
            tm0 = fmaxf(tm0, fmaxf(sc[nt][0], sc[nt][1]));
            tm1 = fmaxf(tm1, fmaxf(sc[nt][2], sc[nt][3]));
        }
        tm0 = fmaxf(tm0, __shfl_xor_sync(0xFFFFFFFF, tm0, 1));
        tm0 = fmaxf(tm0, __shfl_xor_sync(0xFFFFFFFF, tm0, 2));
        tm1 = fmaxf(tm1, __shfl_xor_sync(0xFFFFFFFF, tm1, 1));
        tm1 = fmaxf(tm1, __shfl_xor_sync(0xFFFFFFFF, tm1, 2));
        float mn0 = fmaxf(m0, tm0), mn1 = fmaxf(m1, tm1);
        float scl0 = __expf(m0 - mn0), scl1 = __expf(m1 - mn1);

        unsigned ps[8][2];
        float su0 = 0.f, su1 = 0.f;
#pragma unroll
        for (int nt = 0; nt < 8; nt++) {
            float e0 = __expf(sc[nt][0] - mn0), e1 = __expf(sc[nt][1] - mn0);
            float e2 = __expf(sc[nt][2] - mn1), e3 = __expf(sc[nt][3] - mn1);
            ps[nt][0] = h2pack(e0, e1);
            ps[nt][1] = h2pack(e2, e3);
            float2 f0 = __half22float2(*reinterpret_cast<__half2*>(&ps[nt][0]));
            float2 f1 = __half22float2(*reinterpret_cast<__half2*>(&ps[nt][1]));
            su0 += f0.x + f0.y;
            su1 += f1.x + f1.y;
        }
        su0 += __shfl_xor_sync(0xFFFFFFFF, su0, 1);
        su0 += __shfl_xor_sync(0xFFFFFFFF, su0, 2);
        su1 += __shfl_xor_sync(0xFFFFFFFF, su1, 1);
        su1 += __shfl_xor_sync(0xFFFFFFFF, su1, 2);
        l0 = l0 * scl0 + su0;
        l1 = l1 * scl1 + su1;
        m0 = mn0; m1 = mn1;

        // ---- rescale ----
#pragma unroll
        for (int nt = 0; nt < 16; nt++) {
            acc[nt][0] *= scl0; acc[nt][1] *= scl0;
            acc[nt][2] *= scl1; acc[nt][3] *= scl1;
        }

        // ---- P@V: C-frag == A-frag (no shfl) ----
#pragma unroll
        for (int kt = 0; kt < 4; kt++) {
            unsigned a[4];
            a[0] = ps[2 * kt][0];
            a[1] = ps[2 * kt][1];
            a[2] = ps[2 * kt + 1][0];
            a[3] = ps[2 * kt + 1][1];
#pragma unroll
            for (int nt = 0; nt < 16; nt++) {
                int n = nt * 8 + gid;
                unsigned bfr[2];
                bfr[0] = lds32(vbB + (unsigned)((8 * kt + ctg) * VROWW + n) * 4u);
                bfr[1] = lds32(vbB + (unsigned)((8 * kt + ctg + 4) * VROWW + n) * 4u);
                mma_f16(acc[nt], a, bfr);
            }
        }

        __syncthreads();                        // all warps done with buf
        if (t + 2 < tcount) issue_tile(t + 2, buf);
        asm volatile("cp.async.commit_group;");
    }

    // ---- write split partials ----
    {
        float* pbase = g_pacc + ((size_t)split * Bq * KVq + bk) * AROWS * Dq;
#pragma unroll
        for (int nt = 0; nt < 16; nt++) {
            int col = nt * 8 + 2 * ctg;
            *reinterpret_cast<float2*>(&pbase[(size_t)r0 * Dq + col]) =
                make_float2(acc[nt][0], acc[nt][1]);
            *reinterpret_cast<float2*>(&pbase[(size_t)(r0 + 8) * Dq + col]) =
                make_float2(acc[nt][2], acc[nt][3]);
        }
    }
    if (ctg == 0) {
        int o = (split * Bq * KVq + bk) * AROWS;
        g_pm[o + r0] = m0;      g_pl[o + r0] = l0;
        g_pm[o + r0 + 8] = m1;  g_pl[o + r0 + 8] = l1;
    }
}

// ---------------- combine splits --------------------------------------------
__global__ void combine_kernel() {
    int idx = blockIdx.x * 256 + threadIdx.x;
    if (idx >= Bq * KVq * AROWS * Dq) return;
    int d = idx & 127;
    int r = (idx >> 7) & 63;
    int bk = idx >> 13;
    float M = -FLT_MAX;
#pragma unroll
    for (int sp = 0; sp < NSPLIT; sp++)
        M = fmaxf(M, g_pm[(sp * Bq * KVq + bk) * AROWS + r]);
    float L = 0.f, Y = 0.f;
#pragma unroll
    for (int sp = 0; sp < NSPLIT; sp++) {
        int o = (sp * Bq * KVq + bk) * AROWS + r;
        float w = __expf(g_pm[o] - M);
        L += g_pl[o] * w;
        Y += g_pacc[(size_t)o * Dq + d] * w;
    }
    float y = Y / L;
    int b = bk >> 3, kv = bk & 7;
    int hl = r >> 4, t = r & 15;
    int h = kv * GQ + hl;
    int m = b * Tq + t;
    g_y[(size_t)m * HD + h * Dq + d] = y;
}

// ---------------- launch -----------------------------------------------------
extern "C" void kernel_launch(void* const* d_in, const int* in_sizes, int n_in,
                              void* d_out, int out_size) {
    const float* x  = (const float*)d_in[0];
    const float* fc = (const float*)d_in[1];
    const float* fs = (const float*)d_in[2];
    const int*  pos = (const int*)  d_in[3];
    const float* kc = (const float*)d_in[5];
    const float* vc = (const float*)d_in[6];
    const float* wq = (const float*)d_in[7];
    const float* wk = (const float*)d_in[8];
    const float* wv = (const float*)d_in[9];
    const float* wo = (const float*)d_in[10];
    float* out = (float*)d_out;

    cudaFuncSetAttribute(qkv_kernel, cudaFuncAttributeMaxDynamicSharedMemorySize,
                         GEMM_SMEM_BYTES);
    cudaFuncSetAttribute(out_kernel, cudaFuncAttributeMaxDynamicSharedMemorySize,
                         GEMM_SMEM_BYTES);
    cudaFuncSetAttribute(attn_kernel, cudaFuncAttributeMaxDynamicSharedMemorySize,
                         ATTN_SMEM_BYTES);

    qkv_kernel<<<dim3(NTOT / 128, SPLITK), 256, GEMM_SMEM_BYTES>>>(x, wq, wk, wv);
    rope_q_kernel<<<(QPAIRS + 255) / 256, 256>>>(fc, fs);
    cvt_kv_kernel<<<dim3(Sq * 64 / 256, Bq * KVq, 2), 256>>>(kc, vc, fc, fs, pos);
    attn_kernel<<<NSPLIT * Bq * KVq, 128, ATTN_SMEM_BYTES>>>(pos);  // 4th -> ncu
    combine_kernel<<<(Bq * KVq * AROWS * Dq + 255) / 256, 256>>>();
    out_kernel<<<dim3(DIMq / 128, SPLITKO), 256, GEMM_SMEM_BYTES>>>(wo);
    reduce_out_kernel<<<(M64 * DIMq / 4 + 255) / 256, 256>>>(out);
}

// round 12
// speedup vs baseline: 1.2500x; 1.2500x over previous
#include <cuda_runtime.h>
#include <cuda_bf16.h>
#include <cuda_fp16.h>
#include <math.h>
#include <float.h>

// Problem constants
#define Bq   4
#define Tq   16
#define Sq   4096
#define Hq   32
#define KVq  8
#define Dq   128
#define DIMq 4096
#define HD   (Hq*Dq)          // 4096
#define KVD  (KVq*Dq)         // 1024
#define NTOT (HD + 2*KVD)     // 6144
#define M64  (Bq*Tq)          // 64
#define GQ   (Hq/KVq)         // 4
#define AROWS 64
#define NSPLIT 9
#define SCALE_F 0.08838834764831843f
#define SPLITK  8             // qkv
#define SPLITKO 16            // out proj

// ---------------- scratch ----------------------------------------------------
__device__ float g_qkvp[SPLITK][M64 * NTOT];
__device__ float g_outp[SPLITKO][M64 * DIMq];
__device__ float g_qatt[Bq*KVq*AROWS*Dq];
__device__ float g_knew[M64*KVq*Dq];
__device__ float g_vnew[M64*KVD];
__device__ float g_pacc[(size_t)NSPLIT*Bq*KVq*AROWS*Dq];
__device__ float g_pm  [NSPLIT*Bq*KVq*AROWS];
__device__ float g_pl  [NSPLIT*Bq*KVq*AROWS];
__device__ float g_y   [M64 * HD];

// ================= shared helpers ===========================================
__device__ __forceinline__ unsigned smem_u32(const void* p) {
    unsigned a;
    asm("{ .reg .u64 t; cvta.to.shared.u64 t, %1; cvt.u32.u64 %0, t; }"
        : "=r"(a) : "l"(p));
    return a;
}
__device__ __forceinline__ unsigned f2tf32(float x) {
    unsigned u; asm("cvt.rna.tf32.f32 %0, %1;" : "=r"(u) : "f"(x)); return u;
}
__device__ __forceinline__ unsigned h2pack(float lo, float hi) {
    unsigned r; asm("cvt.rn.f16x2.f32 %0, %1, %2;" : "=r"(r) : "f"(hi), "f"(lo));
    return r;
}
__device__ __forceinline__ void mma_tf32(float c[4], const unsigned a[4], const unsigned b[2]) {
    asm volatile(
        "mma.sync.aligned.m16n8k8.row.col.f32.tf32.tf32.f32 "
        "{%0,%1,%2,%3}, {%4,%5,%6,%7}, {%8,%9}, {%0,%1,%2,%3};\n"
        : "+f"(c[0]), "+f"(c[1]), "+f"(c[2]), "+f"(c[3])
        : "r"(a[0]), "r"(a[1]), "r"(a[2]), "r"(a[3]), "r"(b[0]), "r"(b[1]));
}
__device__ __forceinline__ void mma_f16(float c[4], const unsigned a[4], const unsigned b[2]) {
    asm volatile(
        "mma.sync.aligned.m16n8k16.row.col.f32.f16.f16.f32 "
        "{%0,%1,%2,%3}, {%4,%5,%6,%7}, {%8,%9}, {%0,%1,%2,%3};\n"
        : "+f"(c[0]), "+f"(c[1]), "+f"(c[2]), "+f"(c[3])
        : "r"(a[0]), "r"(a[1]), "r"(a[2]), "r"(a[3]), "r"(b[0]), "r"(b[1]));
}
__device__ __forceinline__ void cpasync16(unsigned saddr, const float* g) {
    asm volatile("cp.async.ca.shared.global [%0], [%1], 16;" :: "r"(saddr), "l"(g));
}
__device__ __forceinline__ void sts32(unsigned baddr, unsigned v) {
    asm volatile("st.shared.u32 [%0], %1;" :: "r"(baddr), "r"(v));
}
__device__ __forceinline__ unsigned lds32(unsigned baddr) {
    unsigned x; asm volatile("ld.shared.u32 %0, [%1];" : "=r"(x) : "r"(baddr));
    return x;
}
__device__ __forceinline__ void lds64(unsigned &x, unsigned &y, unsigned baddr) {
    asm volatile("ld.shared.v2.u32 {%0, %1}, [%2];" : "=r"(x), "=r"(y) : "r"(baddr));
}

// ================= tf32 split-K GEMM, 64x128 block tile, 3-stage ============
// 83 KB smem -> 2 blocks/SM co-resident (16 warps) for latency hiding.
#define BKg      32
#define GSTAGES  3
#define GSTRIDE  36
#define GSTG_FLT (192 * GSTRIDE)
#define GEMM_SMEM_BYTES (GSTAGES * GSTG_FLT * 4)   // 82944
#define GK       4096

__device__ __forceinline__ void gemm_tile_mma(const float* __restrict__ A,
                                              const float* __restrict__ W,
                                              float* __restrict__ Cbase,
                                              int ldc, int kbeg, int nks) {
    extern __shared__ float smf[];
    const int tid  = threadIdx.x;
    const int lane = tid & 31;
    const int wid  = tid >> 5;
    const int gid  = lane >> 2;
    const int ctg  = lane & 3;
    const int wm   = wid & 1;
    const int wn   = wid >> 1;
    const int frA  = tid >> 2;
    const int fkA  = (tid & 3) * 8;
    const int frW  = tid >> 1;
    const int fkW  = (tid & 1) * 16;
    const unsigned sbase = smem_u32(smf);

    float acc[2][4][4];
#pragma unroll
    for (int mi = 0; mi < 2; mi++)
#pragma unroll
        for (int ni = 0; ni < 4; ni++)
#pragma unroll
            for (int j = 0; j < 4; j++) acc[mi][ni][j] = 0.f;

#pragma unroll
    for (int s = 0; s < GSTAGES - 1; s++) {
        unsigned sa = sbase + (unsigned)(s * GSTG_FLT + frA * GSTRIDE + fkA) * 4u;
        unsigned sw = sbase + (unsigned)(s * GSTG_FLT + (64 + frW) * GSTRIDE + fkW) * 4u;
        const float* ga = A + (size_t)frA * GK + kbeg + s * BKg + fkA;
        const float* gw = W + (size_t)frW * GK + kbeg + s * BKg + fkW;
        cpasync16(sa, ga);       cpasync16(sa + 16, ga + 4);
        cpasync16(sw, gw);       cpasync16(sw + 16, gw + 4);
        cpasync16(sw + 32, gw + 8); cpasync16(sw + 48, gw + 12);
        asm volatile("cp.async.commit_group;");
    }

    for (int i = 0; i < nks; i++) {
        asm volatile("cp.async.wait_group 1;");
        __syncthreads();
        int bufi = i % 3;
        const float* As = smf + bufi * GSTG_FLT;
        const float* Ws = As + 64 * GSTRIDE;

#pragma unroll
        for (int ks = 0; ks < 4; ks++) {
            const int k = ks * 8;
            unsigned af[2][4], bf[4][2];
#pragma unroll
            for (int mi = 0; mi < 2; mi++) {
                int r = wm * 32 + mi * 16 + gid;
                af[mi][0] = f2tf32(As[r * GSTRIDE + k + ctg]);
                af[mi][1] = f2tf32(As[(r + 8) * GSTRIDE + k + ctg]);
                af[mi][2] = f2tf32(As[r * GSTRIDE + k + ctg + 4]);
                af[mi][3] = f2tf32(As[(r + 8) * GSTRIDE + k + ctg + 4]);
            }
#pragma unroll
            for (int ni = 0; ni < 4; ni++) {
                int n = wn * 32 + ni * 8 + gid;
                bf[ni][0] = f2tf32(Ws[n * GSTRIDE + k + ctg]);
                bf[ni][1] = f2tf32(Ws[n * GSTRIDE + k + ctg + 4]);
            }
#pragma unroll
            for (int mi = 0; mi < 2; mi++)
#pragma unroll
                for (int ni = 0; ni < 4; ni++)
                    mma_tf32(acc[mi][ni], af[mi], bf[ni]);
        }

        if (i + GSTAGES - 1 < nks) {
            int s = (i + 2) % 3;
            int k0 = kbeg + (i + 2) * BKg;
            unsigned sa = sbase + (unsigned)(s * GSTG_FLT + frA * GSTRIDE + fkA) * 4u;
            unsigned sw = sbase + (unsigned)(s * GSTG_FLT + (64 + frW) * GSTRIDE + fkW) * 4u;
            const float* ga = A + (size_t)frA * GK + k0 + fkA;
            const float* gw = W + (size_t)frW * GK + k0 + fkW;
            cpasync16(sa, ga);       cpasync16(sa + 16, ga + 4);
            cpasync16(sw, gw);       cpasync16(sw + 16, gw + 4);
            cpasync16(sw + 32, gw + 8); cpasync16(sw + 48, gw + 12);
            asm volatile("cp.async.commit_group;");
        } else {
            asm volatile("cp.async.commit_group;");
        }
    }

#pragma unroll
    for (int mi = 0; mi < 2; mi++)
#pragma unroll
        for (int ni = 0; ni < 4; ni++) {
            int r0 = wm * 32 + mi * 16 + gid;
            int c0 = wn * 32 + ni * 8 + 2 * ctg;
            *reinterpret_cast<float2*>(&Cbase[(size_t)r0 * ldc + c0]) =
                make_float2(acc[mi][ni][0], acc[mi][ni][1]);
            *reinterpret_cast<float2*>(&Cbase[(size_t)(r0 + 8) * ldc + c0]) =
                make_float2(acc[mi][ni][2], acc[mi][ni][3]);
        }
}

__global__ void qkv_kernel(const float* __restrict__ x,
                           const float* __restrict__ wq,
                           const float* __restrict__ wk,
                           const float* __restrict__ wv) {
    int n0 = blockIdx.x * 128;
    int sp = blockIdx.y;
    const float* W;
    if (n0 < HD)            W = wq + (size_t)n0 * DIMq;
    else if (n0 < HD + KVD) W = wk + (size_t)(n0 - HD) * DIMq;
    else                    W = wv + (size_t)(n0 - HD - KVD) * DIMq;
    gemm_tile_mma(x, W, g_qkvp[sp] + n0, NTOT, sp * (GK / SPLITK), GK / BKg / SPLITK);
}

__global__ void out_kernel(const float* __restrict__ wo) {
    int n0 = blockIdx.x * 128;
    int sp = blockIdx.y;
    gemm_tile_mma(g_y, wo + (size_t)n0 * DIMq, g_outp[sp] + n0, DIMq,
                  sp * (GK / SPLITKO), GK / BKg / SPLITKO);
}

__global__ void reduce_out_kernel(float* __restrict__ out) {
    int i = blockIdx.x * 256 + threadIdx.x;
    if (i >= M64 * DIMq / 4) return;
    float4 r = reinterpret_cast<const float4*>(g_outp[0])[i];
#pragma unroll
    for (int sp = 1; sp < SPLITKO; sp++) {
        float4 v = reinterpret_cast<const float4*>(g_outp[sp])[i];
        r.x += v.x; r.y += v.y; r.z += v.z; r.w += v.w;
    }
    reinterpret_cast<float4*>(out)[i] = r;
}

// ---------------- fused split-K reduce + RoPE (two kernels) ------------------
#define QPAIRS (M64*Hq*(Dq/2))   // 131072
#define KPAIRS (M64*KVq*(Dq/2))  // 32768
#define VQUADS (M64*KVD/4)       // 16384
__global__ void rope_q_kernel(const float* __restrict__ fc,
                              const float* __restrict__ fs) {
    int idx = blockIdx.x * blockDim.x + threadIdx.x;
    if (idx >= QPAIRS) return;
    int i = idx & 63;
    int h = (idx >> 6) & (Hq - 1);
    int m = idx >> 11;
    int t = m & (Tq - 1), b = m >> 4;
    size_t off = (size_t)m * NTOT + h * Dq + 2 * i;
    float x0 = 0.f, x1 = 0.f;
#pragma unroll
    for (int sp = 0; sp < SPLITK; sp++) {
        float2 p = *reinterpret_cast<const float2*>(&g_qkvp[sp][off]);
        x0 += p.x; x1 += p.y;
    }
    float c = fc[t * 64 + i], s = fs[t * 64 + i];
    int kv = h >> 2, hl = h & 3;
    float* q = g_qatt + ((((size_t)b * KVq + kv) * AROWS) + hl * Tq + t) * Dq + 2 * i;
    q[0] = (x0 * c - x1 * s) * SCALE_F;
    q[1] = (x0 * s + x1 * c) * SCALE_F;
}

__global__ void rope_kv_kernel(const float* __restrict__ fc,
                               const float* __restrict__ fs) {
    int idx = blockIdx.x * blockDim.x + threadIdx.x;
    if (idx < KPAIRS) {
        int i = idx & 63;
        int kv = (idx >> 6) & (KVq - 1);
        int m = idx >> 9;
        int t = m & (Tq - 1);
        size_t off = (size_t)m * NTOT + HD + kv * Dq + 2 * i;
        float x0 = 0.f, x1 = 0.f;
#pragma unroll
        for (int sp = 0; sp < SPLITK; sp++) {
            float2 p = *reinterpret_cast<const float2*>(&g_qkvp[sp][off]);
            x0 += p.x; x1 += p.y;
        }
        float c = fc[t * 64 + i], s = fs[t * 64 + i];
        float* k = g_knew + ((size_t)m * KVq + kv) * Dq + 2 * i;
        k[0] = x0 * c - x1 * s;
        k[1] = x0 * s + x1 * c;
    } else if (idx < KPAIRS + VQUADS) {
        int j = idx - KPAIRS;
        int m = j >> 8;
        int c4 = (j & 255) * 4;
        size_t off = (size_t)m * NTOT + HD + KVD + c4;
        float4 r = make_float4(0.f, 0.f, 0.f, 0.f);
#pragma unroll
        for (int sp = 0; sp < SPLITK; sp++) {
            float4 v = *reinterpret_cast<const float4*>(&g_qkvp[sp][off]);
            r.x += v.x; r.y += v.y; r.z += v.z; r.w += v.w;
        }
        *reinterpret_cast<float4*>(&g_vnew[(size_t)m * KVD + c4]) = r;
    }
}

// ================= tensor-core flash attention v5 (fp16 mma) ================
// 128 threads / 4 warps, warp owns 16 q-rows x all 32 keys.
// fp16 fragments: mma.m16n8k16, fp32 accumulate. K pair-permuted half2 rows
// (stride 72 words, LDS.64 conflict-free). V as key-pair half2 rows (stride
// 136 words, LDS.32 conflict-free). P: QK C-frag == PV A-frag (no shfl).
#define KV_TILE 32
#define KROWW 72                          // K row stride (words)
#define VROWW 136                         // V pair-row stride (words)
#define KB_BYTES (32 * KROWW * 4)         // 9216

__global__ void __launch_bounds__(128, 2)
attn_kernel(const float* __restrict__ k_cache,
            const float* __restrict__ v_cache,
            const int* __restrict__ input_pos) {
    __shared__ unsigned smemA[32 * KROWW + 16 * VROWW];
    __shared__ int pos_s[Tq];

    const int tid  = threadIdx.x;
    const int lane = tid & 31;
    const int gid  = lane >> 2;
    const int ctg  = lane & 3;
    const int wid  = tid >> 5;
    const int r0   = wid * 16 + gid;

    const int bk = blockIdx.x & 31;
    const int split = blockIdx.x >> 5;
    const int b = bk >> 3, kv = bk & 7;

    if (tid < Tq) pos_s[tid] = input_pos[tid];

    const int start_pos = __ldg(&input_pos[0]);
    const int limit = __ldg(&input_pos[Tq - 1]) + 1;
    const int totalTiles = (limit + KV_TILE - 1) / KV_TILE;
    const int tbase = totalTiles / NSPLIT, trem = totalTiles % NSPLIT;
    const int t0 = split * tbase + min(split, trem);
    const int tcount = tbase + (split < trem);
    const int sbeg = t0 * KV_TILE;
    const int send = min((t0 + tcount) * KV_TILE, limit);

    // ---- Q into fp16 registers: 8 k16-chunks x 4 regs ----
    unsigned qreg[8][4];
    {
        const float* qa = g_qatt + (((size_t)b * KVq + kv) * AROWS + r0) * Dq;
        const float* qb = qa + 8 * Dq;
#pragma unroll
        for (int ks = 0; ks < 8; ks++) {
            int c0 = ks * 16 + 2 * ctg;
            qreg[ks][0] = h2pack(qa[c0],     qa[c0 + 1]);
            qreg[ks][1] = h2pack(qb[c0],     qb[c0 + 1]);
            qreg[ks][2] = h2pack(qa[c0 + 8], qa[c0 + 9]);
            qreg[ks][3] = h2pack(qb[c0 + 8], qb[c0 + 9]);
        }
    }

    const unsigned sbK = smem_u32(smemA);
    const unsigned sbV = sbK + KB_BYTES;

    // fill mappings
    const int kr  = tid >> 2;            // K row 0..31
    const int kq  = tid & 3;             // covers d [kq*32, kq*32+32)
    const int vp  = tid >> 3;            // V pair-row 0..15 (keys 2vp, 2vp+1)
    const int vdb = (tid & 7) * 16;      // V d base

    float4 kpre[8], vpre[8];

    auto row_ptr_k = [&](int s) -> const float* {
        if (s >= start_pos && s < start_pos + Tq)
            return &g_knew[((size_t)(b * Tq + (s - start_pos)) * KVq + kv) * Dq];
        return &k_cache[(((size_t)b * Sq + s) * KVq + kv) * Dq];
    };
    auto row_ptr_v = [&](int s) -> const float* {
        if (s >= start_pos && s < start_pos + Tq)
            return &g_vnew[(size_t)(b * Tq + (s - start_pos)) * KVD + kv * Dq];
        return &v_cache[(((size_t)b * Sq + s) * KVq + kv) * Dq];
    };

    auto ldg_tile = [&](int s0t) {
        const float* kp = row_ptr_k(s0t + kr) + kq * 32;
#pragma unroll
        for (int j = 0; j < 8; j++)
            kpre[j] = *reinterpret_cast<const float4*>(kp + j * 4);
        const float* v0 = row_ptr_v(s0t + 2 * vp)     + vdb;
        const float* v1 = row_ptr_v(s0t + 2 * vp + 1) + vdb;
#pragma unroll
        for (int j = 0; j < 4; j++) {
            vpre[j]     = *reinterpret_cast<const float4*>(v0 + j * 4);
            vpre[j + 4] = *reinterpret_cast<const float4*>(v1 + j * 4);
        }
    };

    auto sts_tile = [&]() {
        // K: two k16 chunks (ks=2kq, 2kq+1); chunk layout [w0 w4][w1 w5][w2 w6][w3 w7]
#pragma unroll
        for (int ks = 0; ks < 2; ks++) {
            unsigned cb = sbK + (unsigned)(kr * KROWW) * 4u + (2 * kq + ks) * 32u;
#pragma unroll
            for (int c = 0; c < 8; c++) {
                float4 f = kpre[ks * 4 + (c >> 1)];
                float lo = (c & 1) ? f.z : f.x;
                float hi = (c & 1) ? f.w : f.y;
                sts32(cb + (unsigned)((c & 3) * 8 + (c >> 2) * 4), h2pack(lo, hi));
            }
        }
        // V: pair-row vp, d = vdb..vdb+15: word = half2(V[2vp][d], V[2vp+1][d])
        unsigned vb = sbV + (unsigned)(vp * VROWW + vdb) * 4u;
#pragma unroll
        for (int j = 0; j < 4; j++) {
            float4 a = vpre[j], c = vpre[j + 4];
            sts32(vb + (unsigned)(j * 4 + 0) * 4u, h2pack(a.x, c.x));
            sts32(vb + (unsigned)(j * 4 + 1) * 4u, h2pack(a.y, c.y));
            sts32(vb + (unsigned)(j * 4 + 2) * 4u, h2pack(a.z, c.z));
            sts32(vb + (unsigned)(j * 4 + 3) * 4u, h2pack(a.w, c.w));
        }
    };

    if (tcount > 0) ldg_tile(sbeg);

    float acc[16][4];
#pragma unroll
    for (int nt = 0; nt < 16; nt++)
#pragma unroll
        for (int j = 0; j < 4; j++) acc[nt][j] = 0.f;
    float m0 = -FLT_MAX, m1 = -FLT_MAX, l0 = 0.f, l1 = 0.f;

    for (int t = 0; t < tcount; t++) {
        const int s0 = sbeg + t * KV_TILE;
        __syncthreads();                 // prev tile's readers done
        sts_tile();
        __syncthreads();                 // smem ready
        if (t + 1 < tcount) ldg_tile(s0 + KV_TILE);

        // ---- QK^T: 16 rows x 32 keys, fp16 k16 steps ----
        float sc[4][4];
#pragma unroll
        for (int nt = 0; nt < 4; nt++)
#pragma unroll
            for (int j = 0; j < 4; j++) sc[nt][j] = 0.f;
#pragma unroll
        for (int ks = 0; ks < 8; ks++) {
#pragma unroll
            for (int nt = 0; nt < 4; nt++) {
                int key = nt * 8 + gid;
                unsigned bfr[2];
                lds64(bfr[0], bfr[1],
                      sbK + (unsigned)(key * KROWW) * 4u + (unsigned)(ks * 32 + ctg * 8));
                mma_f16(sc[nt], qreg[ks], bfr);
            }
        }

        // ---- mask + warp-local online softmax ----
        const int p0 = pos_s[gid];
        const int p1 = pos_s[gid + 8];
        float tm0 = -FLT_MAX, tm1 = -FLT_MAX;
#pragma unroll
        for (int nt = 0; nt < 4; nt++) {
            int cb = nt * 8 + 2 * ctg;
            int sA = s0 + cb, sB = sA + 1;
            sc[nt][0] = (sA < send && sA <= p0) ? sc[nt][0] : -FLT_MAX;
            sc[nt][1] = (sB < send && sB <= p0) ? sc[nt][1] : -FLT_MAX;
            sc[nt][2] = (sA < send && sA <= p1) ? sc[nt][2] : -FLT_MAX;
            sc[nt][3] = (sB < send && sB <= p1) ? sc[nt][3] : -FLT_MAX;
            tm0 = fmaxf(tm0, fmaxf(sc[nt][0], sc[nt][1]));
            tm1 = fmaxf(tm1, fmaxf(sc[nt][2], sc[nt][3]));
        }
        tm0 = fmaxf(tm0, __shfl_xor_sync(0xFFFFFFFF, tm0, 1));
        tm0 = fmaxf(tm0, __shfl_xor_sync(0xFFFFFFFF, tm0, 2));
        tm1 = fmaxf(tm1, __shfl_xor_sync(0xFFFFFFFF, tm1, 1));
        tm1 = fmaxf(tm1, __shfl_xor_sync(0xFFFFFFFF, tm1, 2));
        float mn0 = fmaxf(m0, tm0), mn1 = fmaxf(m1, tm1);
        float scl0 = __expf(m0 - mn0), scl1 = __expf(m1 - mn1);

        unsigned ps[4][2];
        float su0 = 0.f, su1 = 0.f;
#pragma unroll
        for (int nt = 0; nt < 4; nt++) {
            float e0 = __expf(sc[nt][0] - mn0), e1 = __expf(sc[nt][1] - mn0);
            float e2 = __expf(sc[nt][2] - mn1), e3 = __expf(sc[nt][3] - mn1);
            ps[nt][0] = h2pack(e0, e1);
            ps[nt][1] = h2pack(e2, e3);
            float2 f0 = __half22float2(*reinterpret_cast<__half2*>(&ps[nt][0]));
            float2 f1 = __half22float2(*reinterpret_cast<__half2*>(&ps[nt][1]));
            su0 += f0.x + f0.y;
            su1 += f1.x + f1.y;
        }
        su0 += __shfl_xor_sync(0xFFFFFFFF, su0, 1);
        su0 += __shfl_xor_sync(0xFFFFFFFF, su0, 2);
        su1 += __shfl_xor_sync(0xFFFFFFFF, su1, 1);
        su1 += __shfl_xor_sync(0xFFFFFFFF, su1, 2);
        l0 = l0 * scl0 + su0;
        l1 = l1 * scl1 + su1;
        m0 = mn0; m1 = mn1;

        // ---- rescale ----
#pragma unroll
        for (int nt = 0; nt < 16; nt++) {
            acc[nt][0] *= scl0; acc[nt][1] *= scl0;
            acc[nt][2] *= scl1; acc[nt][3] *= scl1;
        }

        // ---- P@V: C-frag == A-frag (no shfl), V fragments via LDS.32 ----
#pragma unroll
        for (int kt = 0; kt < 2; kt++) {
            unsigned a[4];
            a[0] = ps[2 * kt][0];
            a[1] = ps[2 * kt][1];
            a[2] = ps[2 * kt + 1][0];
            a[3] = ps[2 * kt + 1][1];
#pragma unroll
            for (int nt = 0; nt < 16; nt++) {
                int n = nt * 8 + gid;
                unsigned bfr[2];
                bfr[0] = lds32(sbV + (unsigned)((8 * kt + ctg) * VROWW + n) * 4u);
                bfr[1] = lds32(sbV + (unsigned)((8 * kt + ctg + 4) * VROWW + n) * 4u);
                mma_f16(acc[nt], a, bfr);
            }
        }
    }

    // ---- write split partials ----
    {
        float* pbase = g_pacc + ((size_t)split * Bq * KVq + bk) * AROWS * Dq;
#pragma unroll
        for (int nt = 0; nt < 16; nt++) {
            int col = nt * 8 + 2 * ctg;
            *reinterpret_cast<float2*>(&pbase[(size_t)r0 * Dq + col]) =
                make_float2(acc[nt][0], acc[nt][1]);
            *reinterpret_cast<float2*>(&pbase[(size_t)(r0 + 8) * Dq + col]) =
                make_float2(acc[nt][2], acc[nt][3]);
        }
    }
    if (ctg == 0) {
        int o = (split * Bq * KVq + bk) * AROWS;
        g_pm[o + r0] = m0;      g_pl[o + r0] = l0;
        g_pm[o + r0 + 8] = m1;  g_pl[o + r0 + 8] = l1;
    }
}

// ---------------- combine splits --------------------------------------------
__global__ void combine_kernel() {
    int idx = blockIdx.x * 256 + threadIdx.x;
    if (idx >= Bq * KVq * AROWS * Dq) return;
    int d = idx & 127;
    int r = (idx >> 7) & 63;
    int bk = idx >> 13;
    float M = -FLT_MAX;
#pragma unroll
    for (int sp = 0; sp < NSPLIT; sp++)
        M = fmaxf(M, g_pm[(sp * Bq * KVq + bk) * AROWS + r]);
    float L = 0.f, Y = 0.f;
#pragma unroll
    for (int sp = 0; sp < NSPLIT; sp++) {
        int o = (sp * Bq * KVq + bk) * AROWS + r;
        float w = __expf(g_pm[o] - M);
        L += g_pl[o] * w;
        Y += g_pacc[(size_t)o * Dq + d] * w;
    }
    float y = Y / L;
    int b = bk >> 3, kv = bk & 7;
    int hl = r >> 4, t = r & 15;
    int h = kv * GQ + hl;
    int m = b * Tq + t;
    g_y[(size_t)m * HD + h * Dq + d] = y;
}

// ---------------- launch -----------------------------------------------------
extern "C" void kernel_launch(void* const* d_in, const int* in_sizes, int n_in,
                              void* d_out, int out_size) {
    const float* x  = (const float*)d_in[0];
    const float* fc = (const float*)d_in[1];
    const float* fs = (const float*)d_in[2];
    const int*  pos = (const int*)  d_in[3];
    const float* kc = (const float*)d_in[5];
    const float* vc = (const float*)d_in[6];
    const float* wq = (const float*)d_in[7];
    const float* wk = (const float*)d_in[8];
    const float* wv = (const float*)d_in[9];
    const float* wo = (const float*)d_in[10];
    float* out = (float*)d_out;

    cudaFuncSetAttribute(qkv_kernel, cudaFuncAttributeMaxDynamicSharedMemorySize,
                         GEMM_SMEM_BYTES);
    cudaFuncSetAttribute(out_kernel, cudaFuncAttributeMaxDynamicSharedMemorySize,
                         GEMM_SMEM_BYTES);

    qkv_kernel<<<dim3(NTOT / 128, SPLITK), 256, GEMM_SMEM_BYTES>>>(x, wq, wk, wv);
    rope_q_kernel<<<(QPAIRS + 255) / 256, 256>>>(fc, fs);
    rope_kv_kernel<<<(KPAIRS + VQUADS + 255) / 256, 256>>>(fc, fs);
    attn_kernel<<<NSPLIT * Bq * KVq, 128>>>(kc, vc, pos);   // 4th launch -> ncu
    combine_kernel<<<(Bq * KVq * AROWS * Dq + 255) / 256, 256>>>();
    out_kernel<<<dim3(DIMq / 128, SPLITKO), 256, GEMM_SMEM_BYTES>>>(wo);
    reduce_out_kernel<<<(M64 * DIMq / 4 + 255) / 256, 256>>>(out);
}